// round 14
// baseline (speedup 1.0000x reference)
#include <cuda_runtime.h>
#include <math.h>

// ---------------- problem constants ----------------
#define BATCH   64
#define SEQ     512
#define EMB     256
#define HID     512
#define GATES   2048           // 4*HID
#define VOCAB   50257
#define NBLK    128            // persistent LSTM grid (<=148 SMs, 1 block/SM)

// ---------------- device scratch (static, no allocs) ----------------
__device__ float g_Z[(size_t)SEQ * BATCH * GATES];   // 256 MB: x@Wi + b, [s][b][4H]
__device__ float g_hQ[2][4][HID * 16];               // h, quarter-contiguous [q][u][b16]
__device__ float g_y1[BATCH * HID];
__device__ float g_y2[BATCH * HID];
__device__ float g_logits[(size_t)BATCH * VOCAB];
// per-block progress flags (dataflow sync): g_prog[(q*32+ub)*32], own 128B line.
// Monotonic per launch; zeroed by reset_kernel (graph-replay-safe).
__device__ unsigned g_prog[128 * 32];

// ---------------- packed f32x2 helpers (FFMA2 path, sm_100+) --------------
__device__ __forceinline__ unsigned long long fma2(unsigned long long a,
                                                   unsigned long long b,
                                                   unsigned long long c)
{
    unsigned long long d;
    asm("fma.rn.f32x2 %0, %1, %2, %3;" : "=l"(d) : "l"(a), "l"(b), "l"(c));
    return d;
}
__device__ __forceinline__ unsigned long long pack2(float x)
{
    unsigned long long d;
    unsigned u = __float_as_uint(x);
    asm("mov.b64 %0, {%1, %1};" : "=l"(d) : "r"(u));
    return d;
}
__device__ __forceinline__ float lo2(unsigned long long v) { return __uint_as_float((unsigned)v); }
__device__ __forceinline__ float hi2(unsigned long long v) { return __uint_as_float((unsigned)(v >> 32)); }

// ---------------- fast activations (MUFU.TANH) ----------------
__device__ __forceinline__ float tanh_fast(float x)
{
    float y;
    asm("tanh.approx.f32 %0, %1;" : "=f"(y) : "f"(x));
    return y;
}
__device__ __forceinline__ float sigmoid_fast(float x)
{
    return 0.5f * tanh_fast(0.5f * x) + 0.5f;
}

// ---------------- cp.async helpers ----------------
__device__ __forceinline__ void cp16(unsigned dst_u32, const void* src)
{
    asm volatile("cp.async.cg.shared.global [%0], [%1], 16;"
                 :: "r"(dst_u32), "l"(src) : "memory");
}
__device__ __forceinline__ void cp_commit()
{
    asm volatile("cp.async.commit_group;" ::: "memory");
}
__device__ __forceinline__ void cp_wait0()
{
    asm volatile("cp.async.wait_group 0;" ::: "memory");
}

// ---------------- kernel 0: reset progress flags (per launch) --------------
__global__ void reset_kernel()
{
    for (int i = threadIdx.x; i < 128 * 32; i += 256) g_prog[i] = 0u;
}

// ---------------- kernel 1: Z = gather(emb, inputs) @ Wi + b --------------
// (R2-proven, unchanged) 128x128 tile, K-chunks of 16, 8x8 thread tile, f32x2.
__global__ void __launch_bounds__(256, 2)
embed_gemm_kernel(const int* __restrict__ inputs, const float* __restrict__ emb,
                  const float* __restrict__ Wi, const float* __restrict__ bias)
{
    __shared__ float As[128][17];
    __shared__ float Bs[16][132];

    const int t  = threadIdx.x;
    const int mt = blockIdx.y;
    const int nt = blockIdx.x;
    const int tx = t & 15;
    const int ty = t >> 4;

    const int ra   = t >> 1;
    const int koff = (t & 1) * 8;
    const int rowg = mt * 128 + ra;
    const int s    = rowg >> 6;
    const int b    = rowg & 63;
    const float* erow = emb + (size_t)inputs[b * SEQ + s] * EMB;

    const int bkr  = t >> 4;
    const int bcol = (t & 15) * 8;

    unsigned long long acc[8][4];
#pragma unroll
    for (int i = 0; i < 8; ++i)
#pragma unroll
        for (int j = 0; j < 4; ++j) acc[i][j] = 0ULL;

    for (int k0 = 0; k0 < EMB; k0 += 16) {
        {
            float4 a0 = *(const float4*)(erow + k0 + koff);
            float4 a1 = *(const float4*)(erow + k0 + koff + 4);
            As[ra][koff + 0] = a0.x; As[ra][koff + 1] = a0.y;
            As[ra][koff + 2] = a0.z; As[ra][koff + 3] = a0.w;
            As[ra][koff + 4] = a1.x; As[ra][koff + 5] = a1.y;
            As[ra][koff + 6] = a1.z; As[ra][koff + 7] = a1.w;
        }
        {
            const float* wsrc = Wi + (size_t)(k0 + bkr) * GATES + nt * 128 + bcol;
            float4 b0v = *(const float4*)(wsrc);
            float4 b1v = *(const float4*)(wsrc + 4);
            *(float4*)&Bs[bkr][bcol]     = b0v;
            *(float4*)&Bs[bkr][bcol + 4] = b1v;
        }
        __syncthreads();

#pragma unroll
        for (int k = 0; k < 16; ++k) {
            unsigned long long pa[8];
#pragma unroll
            for (int i = 0; i < 4; ++i) {
                pa[i]     = pack2(As[ty * 4 + i][k]);
                pa[i + 4] = pack2(As[64 + ty * 4 + i][k]);
            }
            ulonglong2 b0v = *(const ulonglong2*)&Bs[k][tx * 4];
            ulonglong2 b1v = *(const ulonglong2*)&Bs[k][64 + tx * 4];
#pragma unroll
            for (int i = 0; i < 8; ++i) {
                acc[i][0] = fma2(pa[i], b0v.x, acc[i][0]);
                acc[i][1] = fma2(pa[i], b0v.y, acc[i][1]);
                acc[i][2] = fma2(pa[i], b1v.x, acc[i][2]);
                acc[i][3] = fma2(pa[i], b1v.y, acc[i][3]);
            }
        }
        __syncthreads();
    }

    float4 bb0 = *(const float4*)(bias + nt * 128 + tx * 4);
    float4 bb1 = *(const float4*)(bias + nt * 128 + 64 + tx * 4);
#pragma unroll
    for (int i = 0; i < 8; ++i) {
        int row = mt * 128 + ((i < 4) ? (ty * 4 + i) : (64 + ty * 4 + i - 4));
        float* zr = g_Z + (size_t)row * GATES + nt * 128;
        float4 v0, v1;
        v0.x = lo2(acc[i][0]) + bb0.x; v0.y = hi2(acc[i][0]) + bb0.y;
        v0.z = lo2(acc[i][1]) + bb0.z; v0.w = hi2(acc[i][1]) + bb0.w;
        v1.x = lo2(acc[i][2]) + bb1.x; v1.y = hi2(acc[i][2]) + bb1.y;
        v1.z = lo2(acc[i][3]) + bb1.z; v1.w = hi2(acc[i][3]) + bb1.w;
        *(float4*)(zr + tx * 4)      = v0;
        *(float4*)(zr + 64 + tx * 4) = v1;
    }
}

// ---------------- kernel 2: persistent LSTM over 512 steps ----------------
// (R11-R13-proven core) 128 blocks = 32 unit-groups x 4 batch-quarters;
// block = 16 units x 16 batches; warp = kc strip (broadcast LDS);
// warp-private cp.async staging; quarter-contiguous h.
// NEW vs R13: DATAFLOW SYNC. The quarter barrier is replaced by per-block
// progress flags. Warp kc's strip (units [kc*64,kc*64+64)) is produced by
// exactly blocks ub = 4kc..4kc+3 of the same quarter -> each warp gates its
// staging on only those 4 flags (lanes 0-3 poll in parallel). No full-quarter
// convergence point; skew pipelines across warps instead of accumulating.
// Double-buffered h bounds skew to 1 step (block needs ALL 32 flags >= s to
// reach step s+1, so no writer can lap a reader).
#define LSTM_SMEM (32768 + 131072 + 36864)

__global__ void __launch_bounds__(256, 1)
lstm_kernel(const float* __restrict__ Wh)
{
    extern __shared__ float sm[];
    float4*     h_s4 = (float4*)sm;                           // [512][4]
    ulonglong2* Whs  = (ulonglong2*)((char*)sm + 32768);      // [512][16]
    ulonglong2* red  = (ulonglong2*)((char*)sm + 163840);     // [256 p][9]

    const int tid  = threadIdx.x;
    const int kc   = tid >> 5;           // warp id = k-strip 0..7 (64 k each)
    const int lane = tid & 31;
    const int up   = lane >> 2;          // unit pair 0..7 (units 2up, 2up+1)
    const int bg   = lane & 3;           // batch group 0..3 (4 batches)
    const int ub   = blockIdx.x >> 2;    // unit group 0..31 (16 units)
    const int q    = blockIdx.x & 3;     // batch quarter 0..3 (16 batches)
    const unsigned h_s_u32 = (unsigned)__cvta_generic_to_shared(h_s4);

    // my published flag; the 4 producer flags my warp waits on
    unsigned* myflag = &g_prog[(q * 32 + ub) * 32];
    const unsigned* prodflag =
        (lane < 4) ? &g_prog[(q * 32 + kc * 4 + lane) * 32] : 0;

    // epilogue ownership: pair p = tid -> unit u_local, batch b_local
    const int eul = tid >> 4;            // 0..15
    const int ebl = tid & 15;            // 0..15
    const int euu = ub * 16 + eul;       // global unit
    const int egb = q * 16 + ebl;        // global batch

    // stage Wh slice once: Whs[k*16+u] = {(wi,wf),(wg,wo)} for col = ub*16+u
    for (int i = tid; i < HID * 16; i += 256) {
        int k = i >> 4, u2 = i & 15;
        const float* w = Wh + (size_t)k * GATES + ub * 16 + u2;
        float4 v = make_float4(w[0], w[512], w[1024], w[1536]);
        Whs[i] = *(ulonglong2*)&v;
    }

    float c = 0.0f;                      // cell state of pair p = tid
    __syncthreads();

    const ulonglong2* wp = Whs  + kc * 1024 + up * 2;  // iter i: wp[i*16], +1
    const float4*     hp = h_s4 + kc * 256 + bg;       // iter i: hp[i*4]

    // warp-private staging: warp kc owns f4-chunks [kc*256, kc*256+256).
    const int cbase = kc * 256 + lane;                 // 8 chunks per lane

    // Z prefetch for step 0 (gates for pair p)
    const float* z0 = g_Z + (size_t)egb * GATES + euu;
    float zi = __ldcg(z0), zf = __ldcg(z0 + 512);
    float zg = __ldcg(z0 + 1024), zo = __ldcg(z0 + 1536);

    for (int s = 0; s < SEQ; ++s) {
        unsigned long long aif[2][4] = {{0,0,0,0},{0,0,0,0}};
        unsigned long long ago[2][4] = {{0,0,0,0},{0,0,0,0}};

        if (s > 0) {
            // ---- dataflow wait: only this warp's 4 strip producers ----
            if (lane < 4) {
                unsigned v;
                do {
                    asm volatile("ld.global.acquire.gpu.u32 %0, [%1];"
                                 : "=r"(v) : "l"(prodflag) : "memory");
                } while (v < (unsigned)s);
            }
            __syncwarp();

            // ---- warp-private staging of this warp's h strip (4KB, dense) --
            const float4* src4 = (const float4*)g_hQ[s & 1][q];
#pragma unroll
            for (int j = 0; j < 8; ++j) {
                int chunk = cbase + j * 32;             // within own strip
                cp16(h_s_u32 + chunk * 16, src4 + chunk);
            }
            cp_commit();
            cp_wait0();        // own 8 copies landed
            __syncwarp();      // all 32 lanes done -> strip complete

            // ---- mainloop: k fixed per iteration, all LDS broadcast ----
#pragma unroll 4
            for (int i = 0; i < 64; ++i) {
                ulonglong2 w0 = wp[i * 16];      // unit 2up   (wi,wf),(wg,wo)
                ulonglong2 w1 = wp[i * 16 + 1];  // unit 2up+1
                float4     hv = hp[i * 4];       // 4 batches
                unsigned long long p;
                p = pack2(hv.x);
                aif[0][0] = fma2(p, w0.x, aif[0][0]); ago[0][0] = fma2(p, w0.y, ago[0][0]);
                aif[1][0] = fma2(p, w1.x, aif[1][0]); ago[1][0] = fma2(p, w1.y, ago[1][0]);
                p = pack2(hv.y);
                aif[0][1] = fma2(p, w0.x, aif[0][1]); ago[0][1] = fma2(p, w0.y, ago[0][1]);
                aif[1][1] = fma2(p, w1.x, aif[1][1]); ago[1][1] = fma2(p, w1.y, ago[1][1]);
                p = pack2(hv.z);
                aif[0][2] = fma2(p, w0.x, aif[0][2]); ago[0][2] = fma2(p, w0.y, ago[0][2]);
                aif[1][2] = fma2(p, w1.x, aif[1][2]); ago[1][2] = fma2(p, w1.y, ago[1][2]);
                p = pack2(hv.w);
                aif[0][3] = fma2(p, w0.x, aif[0][3]); ago[0][3] = fma2(p, w0.y, ago[0][3]);
                aif[1][3] = fma2(p, w1.x, aif[1][3]); ago[1][3] = fma2(p, w1.y, ago[1][3]);
            }
        }

        // ---- write partials to skewed red[p*9 + kc] ----
#pragma unroll
        for (int uo = 0; uo < 2; ++uo)
#pragma unroll
            for (int bi = 0; bi < 4; ++bi) {
                int p = (2 * up + uo) * 16 + bg * 4 + bi;
                red[p * 9 + kc] = make_ulonglong2(aif[uo][bi], ago[uo][bi]);
            }
        __syncthreads();

        // ---- reduce 8 kc partials for pair p = tid; epilogue ----
        {
            float fi = zi, ff = zf, fg_ = zg, fo = zo;
#pragma unroll
            for (int k8 = 0; k8 < 8; ++k8) {
                ulonglong2 v = red[tid * 9 + k8];
                fi += lo2(v.x); ff += hi2(v.x);
                fg_ += lo2(v.y); fo += hi2(v.y);
            }
            float ig  = sigmoid_fast(fi);
            float fg2 = sigmoid_fast(ff);
            float gg  = tanh_fast(fg_);
            float og  = sigmoid_fast(fo);
            c = fg2 * c + ig * gg;
            float hv = og * tanh_fast(c);
            // quarter-contiguous store: [q][u][b16]; final h in g_hQ[0]
            g_hQ[(s + 1) & 1][q][euu * 16 + ebl] = hv;
        }

        // ---- prefetch Z for step s+1 (overlaps flag publish / next poll) --
        if (s + 1 < SEQ) {
            const float* z = g_Z + ((size_t)(s + 1) * BATCH + egb) * GATES + euu;
            zi = __ldcg(z);        zf = __ldcg(z + 512);
            zg = __ldcg(z + 1024); zo = __ldcg(z + 1536);
        }

        // ---- publish progress: h stores (all threads) -> sync -> release ---
        __syncthreads();   // h stores done block-wide; also red WAR protection
        if (tid == 0) {
            asm volatile("st.global.release.gpu.u32 [%0], %1;"
                         :: "l"(myflag), "r"((unsigned)(s + 1)) : "memory");
        }
    }
}

// ---------------- kernels 3/4: y = tanh(x @ W + bias), 64x512 --------------
// Block = one batch row (64 blocks x 512 threads); x row staged in smem.
// KM=1: x is quarter-contiguous h (g_hQ[0]): x[(b>>4)*8192 + (b&15) + k*16].
// KM=0: x is batch-major [b][k]: x[b*512 + k].
template<int KM>
__global__ void __launch_bounds__(512)
fc_tanh_kernel(const float* __restrict__ x, const float* __restrict__ W,
               const float* __restrict__ bias, float* __restrict__ y)
{
    __shared__ float xs[HID];
    const int b = blockIdx.x;
    const int j = threadIdx.x;

    if (KM == 1)
        xs[j] = x[(b >> 4) * 8192 + (b & 15) + j * 16];
    else
        xs[j] = x[b * HID + j];
    __syncthreads();

    float a0 = 0.f, a1 = 0.f, a2 = 0.f, a3 = 0.f;
#pragma unroll 4
    for (int k = 0; k < HID; k += 4) {
        a0 += xs[k + 0] * W[(size_t)(k + 0) * HID + j];
        a1 += xs[k + 1] * W[(size_t)(k + 1) * HID + j];
        a2 += xs[k + 2] * W[(size_t)(k + 2) * HID + j];
        a3 += xs[k + 3] * W[(size_t)(k + 3) * HID + j];
    }
    y[b * HID + j] = tanhf((a0 + a1) + (a2 + a3) + bias[j]);
}

// ---------------- kernel 5: logits = y2 @ W3 + b3 (f32x2 accumulators) -----
__global__ void __launch_bounds__(128)
logits_kernel(const float* __restrict__ y, const float* __restrict__ W3,
              const float* __restrict__ b3, float* __restrict__ out)
{
    __shared__ __align__(16) float ys[128][68];   // [k][b], row = 272B (16B-mult)
    const int j = blockIdx.x * 128 + threadIdx.x;

    unsigned long long acc[32];
#pragma unroll
    for (int i = 0; i < 32; ++i) acc[i] = 0ULL;

    for (int kc = 0; kc < HID; kc += 128) {
        __syncthreads();
        for (int qq = threadIdx.x; qq < 128 * 64; qq += 128) {
            int b = qq >> 7, k = qq & 127;
            ys[k][b] = y[b * HID + kc + k];
        }
        __syncthreads();
        if (j < VOCAB) {
#pragma unroll 4
            for (int k = 0; k < 128; ++k) {
                unsigned long long wpk = pack2(W3[(size_t)(kc + k) * VOCAB + j]);
                const ulonglong2* yr = (const ulonglong2*)&ys[k][0];
#pragma unroll
                for (int b2 = 0; b2 < 16; ++b2) {
                    ulonglong2 v = yr[b2];                  // batches 4b2..4b2+3
                    acc[b2 * 2]     = fma2(wpk, v.x, acc[b2 * 2]);
                    acc[b2 * 2 + 1] = fma2(wpk, v.y, acc[b2 * 2 + 1]);
                }
            }
        }
    }
    if (j < VOCAB) {
        float bb = b3[j];
#pragma unroll
        for (int i = 0; i < 32; ++i) {
            out[(size_t)(2 * i)     * VOCAB + j] = lo2(acc[i]) + bb;
            out[(size_t)(2 * i + 1) * VOCAB + j] = hi2(acc[i]) + bb;
        }
    }
}

// ---------------- kernel 6: row-wise log_softmax ----------------
__global__ void __launch_bounds__(1024)
logsoftmax_kernel(const float* __restrict__ logits, float* __restrict__ out)
{
    __shared__ float red[32];
    const int b = blockIdx.x;
    const float* row  = logits + (size_t)b * VOCAB;
    float*       orow = out    + (size_t)b * VOCAB;
    const int tid = threadIdx.x;

    float m = -1e30f;
    for (int j = tid; j < VOCAB; j += 1024) m = fmaxf(m, row[j]);
#pragma unroll
    for (int o = 16; o; o >>= 1) m = fmaxf(m, __shfl_xor_sync(0xffffffffu, m, o));
    if ((tid & 31) == 0) red[tid >> 5] = m;
    __syncthreads();
    if (tid < 32) {
        float v = red[tid];
#pragma unroll
        for (int o = 16; o; o >>= 1) v = fmaxf(v, __shfl_xor_sync(0xffffffffu, v, o));
        red[tid] = v;
    }
    __syncthreads();
    m = red[0];

    float sum = 0.0f;
    for (int j = tid; j < VOCAB; j += 1024) sum += __expf(row[j] - m);
#pragma unroll
    for (int o = 16; o; o >>= 1) sum += __shfl_xor_sync(0xffffffffu, sum, o);
    __syncthreads();
    if ((tid & 31) == 0) red[tid >> 5] = sum;
    __syncthreads();
    if (tid < 32) {
        float v = red[tid];
#pragma unroll
        for (int o = 16; o; o >>= 1) v += __shfl_xor_sync(0xffffffffu, v, o);
        red[tid] = v;
    }
    __syncthreads();
    float lse = m + logf(red[0]);

    for (int j = tid; j < VOCAB; j += 1024) orow[j] = row[j] - lse;
}

// ---------------- launch ----------------
extern "C" void kernel_launch(void* const* d_in, const int* in_sizes, int n_in,
                              void* d_out, int out_size)
{
    const int*   inputs = (const int*)  d_in[0];
    const float* emb    = (const float*)d_in[1];
    const float* Wi     = (const float*)d_in[2];
    const float* Wh     = (const float*)d_in[3];
    const float* bvec   = (const float*)d_in[4];
    const float* W1     = (const float*)d_in[5];
    const float* b1     = (const float*)d_in[6];
    const float* W2     = (const float*)d_in[7];
    const float* b2     = (const float*)d_in[8];
    const float* W3     = (const float*)d_in[9];
    const float* b3     = (const float*)d_in[10];
    float* out = (float*)d_out;

    void *p_h = 0, *p_y1 = 0, *p_y2 = 0, *p_lg = 0;
    cudaGetSymbolAddress(&p_h,  g_hQ);     // final h in g_hQ[0], [q][u][b16]
    cudaGetSymbolAddress(&p_y1, g_y1);
    cudaGetSymbolAddress(&p_y2, g_y2);
    cudaGetSymbolAddress(&p_lg, g_logits);

    // 0. reset progress flags (replay-safe)
    reset_kernel<<<1, 256>>>();

    // 1. Z = emb[inputs] @ Wi + b  (time-parallel)
    embed_gemm_kernel<<<dim3(GATES / 128, (SEQ * BATCH) / 128), 256>>>(inputs, emb, Wi, bvec);

    // 2. persistent LSTM recurrence (dataflow-synced)
    cudaFuncSetAttribute(lstm_kernel, cudaFuncAttributeMaxDynamicSharedMemorySize, LSTM_SMEM);
    lstm_kernel<<<NBLK, 256, LSTM_SMEM>>>(Wh);

    // 3/4. dense tanh layers (fc1 reads quarter-contiguous h)
    fc_tanh_kernel<1><<<BATCH, 512>>>((const float*)p_h,  W1, b1, (float*)p_y1);
    fc_tanh_kernel<0><<<BATCH, 512>>>((const float*)p_y1, W2, b2, (float*)p_y2);

    // 5. vocab projection
    logits_kernel<<<(VOCAB + 127) / 128, 128>>>((const float*)p_y2, W3, b3, (float*)p_lg);

    // 6. log_softmax
    logsoftmax_kernel<<<BATCH, 1024>>>((const float*)p_lg, out);
}

// round 15
// speedup vs baseline: 1.1424x; 1.1424x over previous
#include <cuda_runtime.h>
#include <math.h>

// ---------------- problem constants ----------------
#define BATCH   64
#define SEQ     512
#define EMB     256
#define HID     512
#define GATES   2048           // 4*HID
#define VOCAB   50257
#define NBLK    128            // persistent LSTM grid (<=148 SMs, 1 block/SM)

// ---------------- device scratch (static, no allocs) ----------------
__device__ float g_Z[(size_t)SEQ * BATCH * GATES];   // 256 MB: x@Wi + b, [s][b][4H]
__device__ float g_hQ[2][4][HID * 16];               // h, quarter-contiguous [q][u][b16]
__device__ float g_y1[BATCH * HID];
__device__ float g_y2[BATCH * HID];
__device__ float g_logits[(size_t)BATCH * VOCAB];
// 4 independent batch-quarter barriers, each on its own 128B line.
// Sense-reversing: after 512 steps (even) state returns to 0 -> replay-safe.
__device__ unsigned g_bar_cnt4[4 * 32];
__device__ unsigned g_bar_sense4[4 * 32];

// ---------------- packed f32x2 helpers (FFMA2 path, sm_100+) --------------
__device__ __forceinline__ unsigned long long fma2(unsigned long long a,
                                                   unsigned long long b,
                                                   unsigned long long c)
{
    unsigned long long d;
    asm("fma.rn.f32x2 %0, %1, %2, %3;" : "=l"(d) : "l"(a), "l"(b), "l"(c));
    return d;
}
__device__ __forceinline__ unsigned long long pack2(float x)
{
    unsigned long long d;
    unsigned u = __float_as_uint(x);
    asm("mov.b64 %0, {%1, %1};" : "=l"(d) : "r"(u));
    return d;
}
__device__ __forceinline__ float lo2(unsigned long long v) { return __uint_as_float((unsigned)v); }
__device__ __forceinline__ float hi2(unsigned long long v) { return __uint_as_float((unsigned)(v >> 32)); }

// ---------------- fast activations (MUFU.TANH) ----------------
__device__ __forceinline__ float tanh_fast(float x)
{
    float y;
    asm("tanh.approx.f32 %0, %1;" : "=f"(y) : "f"(x));
    return y;
}
__device__ __forceinline__ float sigmoid_fast(float x)
{
    return 0.5f * tanh_fast(0.5f * x) + 0.5f;
}

// ---------------- group grid barrier (R7/R13-proven, n arrivals) ----------
__device__ __forceinline__ void grid_barrier_g(unsigned &sense, unsigned* cnt,
                                               unsigned* flag, unsigned n)
{
    __syncthreads();
    if (threadIdx.x == 0) {
        sense ^= 1u;
        unsigned old;
        asm volatile("atom.add.release.gpu.global.u32 %0, [%1], %2;"
                     : "=r"(old) : "l"(cnt), "r"(1u) : "memory");
        if (old == n - 1u) {
            asm volatile("st.global.relaxed.gpu.u32 [%0], %1;"
                         :: "l"(cnt), "r"(0u) : "memory");
            asm volatile("st.global.release.gpu.u32 [%0], %1;"
                         :: "l"(flag), "r"(sense) : "memory");
        } else {
            unsigned v;
            do {
                asm volatile("ld.global.acquire.gpu.u32 %0, [%1];"
                             : "=r"(v) : "l"(flag) : "memory");
            } while (v != sense);
        }
    }
    __syncthreads();
}

// ---------------- kernel 1: Z = gather(emb, inputs) @ Wi + b --------------
// (R2-proven, unchanged) 128x128 tile, K-chunks of 16, 8x8 thread tile, f32x2.
__global__ void __launch_bounds__(256, 2)
embed_gemm_kernel(const int* __restrict__ inputs, const float* __restrict__ emb,
                  const float* __restrict__ Wi, const float* __restrict__ bias)
{
    __shared__ float As[128][17];
    __shared__ float Bs[16][132];

    const int t  = threadIdx.x;
    const int mt = blockIdx.y;
    const int nt = blockIdx.x;
    const int tx = t & 15;
    const int ty = t >> 4;

    const int ra   = t >> 1;
    const int koff = (t & 1) * 8;
    const int rowg = mt * 128 + ra;
    const int s    = rowg >> 6;
    const int b    = rowg & 63;
    const float* erow = emb + (size_t)inputs[b * SEQ + s] * EMB;

    const int bkr  = t >> 4;
    const int bcol = (t & 15) * 8;

    unsigned long long acc[8][4];
#pragma unroll
    for (int i = 0; i < 8; ++i)
#pragma unroll
        for (int j = 0; j < 4; ++j) acc[i][j] = 0ULL;

    for (int k0 = 0; k0 < EMB; k0 += 16) {
        {
            float4 a0 = *(const float4*)(erow + k0 + koff);
            float4 a1 = *(const float4*)(erow + k0 + koff + 4);
            As[ra][koff + 0] = a0.x; As[ra][koff + 1] = a0.y;
            As[ra][koff + 2] = a0.z; As[ra][koff + 3] = a0.w;
            As[ra][koff + 4] = a1.x; As[ra][koff + 5] = a1.y;
            As[ra][koff + 6] = a1.z; As[ra][koff + 7] = a1.w;
        }
        {
            const float* wsrc = Wi + (size_t)(k0 + bkr) * GATES + nt * 128 + bcol;
            float4 b0v = *(const float4*)(wsrc);
            float4 b1v = *(const float4*)(wsrc + 4);
            *(float4*)&Bs[bkr][bcol]     = b0v;
            *(float4*)&Bs[bkr][bcol + 4] = b1v;
        }
        __syncthreads();

#pragma unroll
        for (int k = 0; k < 16; ++k) {
            unsigned long long pa[8];
#pragma unroll
            for (int i = 0; i < 4; ++i) {
                pa[i]     = pack2(As[ty * 4 + i][k]);
                pa[i + 4] = pack2(As[64 + ty * 4 + i][k]);
            }
            ulonglong2 b0v = *(const ulonglong2*)&Bs[k][tx * 4];
            ulonglong2 b1v = *(const ulonglong2*)&Bs[k][64 + tx * 4];
#pragma unroll
            for (int i = 0; i < 8; ++i) {
                acc[i][0] = fma2(pa[i], b0v.x, acc[i][0]);
                acc[i][1] = fma2(pa[i], b0v.y, acc[i][1]);
                acc[i][2] = fma2(pa[i], b1v.x, acc[i][2]);
                acc[i][3] = fma2(pa[i], b1v.y, acc[i][3]);
            }
        }
        __syncthreads();
    }

    float4 bb0 = *(const float4*)(bias + nt * 128 + tx * 4);
    float4 bb1 = *(const float4*)(bias + nt * 128 + 64 + tx * 4);
#pragma unroll
    for (int i = 0; i < 8; ++i) {
        int row = mt * 128 + ((i < 4) ? (ty * 4 + i) : (64 + ty * 4 + i - 4));
        float* zr = g_Z + (size_t)row * GATES + nt * 128;
        float4 v0, v1;
        v0.x = lo2(acc[i][0]) + bb0.x; v0.y = hi2(acc[i][0]) + bb0.y;
        v0.z = lo2(acc[i][1]) + bb0.z; v0.w = hi2(acc[i][1]) + bb0.w;
        v1.x = lo2(acc[i][2]) + bb1.x; v1.y = hi2(acc[i][2]) + bb1.y;
        v1.z = lo2(acc[i][3]) + bb1.z; v1.w = hi2(acc[i][3]) + bb1.w;
        *(float4*)(zr + tx * 4)      = v0;
        *(float4*)(zr + 64 + tx * 4) = v1;
    }
}

// ---------------- kernel 2: persistent LSTM over 512 steps ----------------
// (R13-proven core + quarter barrier) 128 blocks = 32 unit-groups x 4
// batch-quarters; block = 16 units x 16 batches; warp = kc strip.
// NEW vs R13: NO smem staging of h. Each warp's strip is read exactly once
// per step and is warp-private, so staging bought zero reuse while adding a
// fully-exposed cp.async wait. The mainloop now reads h directly from L2 via
// __ldcg(float4); 64 independent iterations let ptxas pipeline the loads so
// L2 latency folds under the fma2 chain. Same traffic (4-lane broadcast
// dedup), one less sync, 32KB less smem.
#define LSTM_SMEM (131072 + 36864)

__global__ void __launch_bounds__(256, 1)
lstm_kernel(const float* __restrict__ Wh)
{
    extern __shared__ float sm[];
    ulonglong2* Whs = (ulonglong2*)sm;                        // [512][16] 128KB
    ulonglong2* red = (ulonglong2*)((char*)sm + 131072);      // [256 p][9]

    const int tid  = threadIdx.x;
    const int kc   = tid >> 5;           // warp id = k-strip 0..7 (64 k each)
    const int lane = tid & 31;
    const int up   = lane >> 2;          // unit pair 0..7 (units 2up, 2up+1)
    const int bg   = lane & 3;           // batch group 0..3 (4 batches)
    const int ub   = blockIdx.x >> 2;    // unit group 0..31 (16 units)
    const int q    = blockIdx.x & 3;     // batch quarter 0..3 (16 batches)

    unsigned* cntp = &g_bar_cnt4[q * 32];
    unsigned* snsp = &g_bar_sense4[q * 32];

    // epilogue ownership: pair p = tid -> unit u_local, batch b_local
    const int eul = tid >> 4;            // 0..15
    const int ebl = tid & 15;            // 0..15
    const int euu = ub * 16 + eul;       // global unit
    const int egb = q * 16 + ebl;        // global batch

    // stage Wh slice once: Whs[k*16+u] = {(wi,wf),(wg,wo)} for col = ub*16+u
    for (int i = tid; i < HID * 16; i += 256) {
        int k = i >> 4, u2 = i & 15;
        const float* w = Wh + (size_t)k * GATES + ub * 16 + u2;
        float4 v = make_float4(w[0], w[512], w[1024], w[1536]);
        Whs[i] = *(ulonglong2*)&v;
    }

    float c = 0.0f;                      // cell state of pair p = tid
    unsigned sense = 0;
    __syncthreads();

    const ulonglong2* wp = Whs + kc * 1024 + up * 2;   // iter i: wp[i*16], +1

    // Z prefetch for step 0 (gates for pair p)
    const float* z0 = g_Z + (size_t)egb * GATES + euu;
    float zi = __ldcg(z0), zf = __ldcg(z0 + 512);
    float zg = __ldcg(z0 + 1024), zo = __ldcg(z0 + 1536);

    for (int s = 0; s < SEQ; ++s) {
        unsigned long long aif[2][4] = {{0,0,0,0},{0,0,0,0}};
        unsigned long long ago[2][4] = {{0,0,0,0},{0,0,0,0}};

        if (s > 0) {
            // h strip for this warp, read straight from L2 (quarter-dense):
            // iter i -> h[kc*64+i][bg*4 .. bg*4+3]
            const float4* hsrc =
                (const float4*)g_hQ[s & 1][q] + kc * 256 + bg;

            // ---- mainloop: k fixed per iteration; w from smem (broadcast),
            //      h via pipelined __ldcg (L2 latency folds under fma2) ----
#pragma unroll 8
            for (int i = 0; i < 64; ++i) {
                float4     hv = __ldcg(hsrc + i * 4);   // 4 batches
                ulonglong2 w0 = wp[i * 16];      // unit 2up   (wi,wf),(wg,wo)
                ulonglong2 w1 = wp[i * 16 + 1];  // unit 2up+1
                unsigned long long p;
                p = pack2(hv.x);
                aif[0][0] = fma2(p, w0.x, aif[0][0]); ago[0][0] = fma2(p, w0.y, ago[0][0]);
                aif[1][0] = fma2(p, w1.x, aif[1][0]); ago[1][0] = fma2(p, w1.y, ago[1][0]);
                p = pack2(hv.y);
                aif[0][1] = fma2(p, w0.x, aif[0][1]); ago[0][1] = fma2(p, w0.y, ago[0][1]);
                aif[1][1] = fma2(p, w1.x, aif[1][1]); ago[1][1] = fma2(p, w1.y, ago[1][1]);
                p = pack2(hv.z);
                aif[0][2] = fma2(p, w0.x, aif[0][2]); ago[0][2] = fma2(p, w0.y, ago[0][2]);
                aif[1][2] = fma2(p, w1.x, aif[1][2]); ago[1][2] = fma2(p, w1.y, ago[1][2]);
                p = pack2(hv.w);
                aif[0][3] = fma2(p, w0.x, aif[0][3]); ago[0][3] = fma2(p, w0.y, ago[0][3]);
                aif[1][3] = fma2(p, w1.x, aif[1][3]); ago[1][3] = fma2(p, w1.y, ago[1][3]);
            }
        }

        // ---- write partials to skewed red[p*9 + kc] ----
#pragma unroll
        for (int uo = 0; uo < 2; ++uo)
#pragma unroll
            for (int bi = 0; bi < 4; ++bi) {
                int p = (2 * up + uo) * 16 + bg * 4 + bi;
                red[p * 9 + kc] = make_ulonglong2(aif[uo][bi], ago[uo][bi]);
            }
        __syncthreads();

        // ---- reduce 8 kc partials for pair p = tid; epilogue ----
        {
            float fi = zi, ff = zf, fg_ = zg, fo = zo;
#pragma unroll
            for (int k8 = 0; k8 < 8; ++k8) {
                ulonglong2 v = red[tid * 9 + k8];
                fi += lo2(v.x); ff += hi2(v.x);
                fg_ += lo2(v.y); fo += hi2(v.y);
            }
            float ig  = sigmoid_fast(fi);
            float fg2 = sigmoid_fast(ff);
            float gg  = tanh_fast(fg_);
            float og  = sigmoid_fast(fo);
            c = fg2 * c + ig * gg;
            float hv = og * tanh_fast(c);
            // quarter-contiguous store: [q][u][b16]; final h in g_hQ[0]
            g_hQ[(s + 1) & 1][q][euu * 16 + ebl] = hv;
        }

        // ---- prefetch Z for step s+1 (hides DRAM latency behind barrier) --
        if (s + 1 < SEQ) {
            const float* z = g_Z + ((size_t)(s + 1) * BATCH + egb) * GATES + euu;
            zi = __ldcg(z);        zf = __ldcg(z + 512);
            zg = __ldcg(z + 1024); zo = __ldcg(z + 1536);
        }

        grid_barrier_g(sense, cntp, snsp, 32u);   // only this batch quarter
    }
}

// ---------------- kernels 3/4: y = tanh(x @ W + bias), 64x512 --------------
// Block = one batch row (64 blocks x 512 threads); x row staged in smem.
// KM=1: x is quarter-contiguous h (g_hQ[0]): x[(b>>4)*8192 + (b&15) + k*16].
// KM=0: x is batch-major [b][k]: x[b*512 + k].
template<int KM>
__global__ void __launch_bounds__(512)
fc_tanh_kernel(const float* __restrict__ x, const float* __restrict__ W,
               const float* __restrict__ bias, float* __restrict__ y)
{
    __shared__ float xs[HID];
    const int b = blockIdx.x;
    const int j = threadIdx.x;

    if (KM == 1)
        xs[j] = x[(b >> 4) * 8192 + (b & 15) + j * 16];
    else
        xs[j] = x[b * HID + j];
    __syncthreads();

    float a0 = 0.f, a1 = 0.f, a2 = 0.f, a3 = 0.f;
#pragma unroll 4
    for (int k = 0; k < HID; k += 4) {
        a0 += xs[k + 0] * W[(size_t)(k + 0) * HID + j];
        a1 += xs[k + 1] * W[(size_t)(k + 1) * HID + j];
        a2 += xs[k + 2] * W[(size_t)(k + 2) * HID + j];
        a3 += xs[k + 3] * W[(size_t)(k + 3) * HID + j];
    }
    y[b * HID + j] = tanhf((a0 + a1) + (a2 + a3) + bias[j]);
}

// ---------------- kernel 5: logits = y2 @ W3 + b3 (f32x2 accumulators) -----
__global__ void __launch_bounds__(128)
logits_kernel(const float* __restrict__ y, const float* __restrict__ W3,
              const float* __restrict__ b3, float* __restrict__ out)
{
    __shared__ __align__(16) float ys[128][68];   // [k][b], row = 272B (16B-mult)
    const int j = blockIdx.x * 128 + threadIdx.x;

    unsigned long long acc[32];
#pragma unroll
    for (int i = 0; i < 32; ++i) acc[i] = 0ULL;

    for (int kc = 0; kc < HID; kc += 128) {
        __syncthreads();
        for (int qq = threadIdx.x; qq < 128 * 64; qq += 128) {
            int b = qq >> 7, k = qq & 127;
            ys[k][b] = y[b * HID + kc + k];
        }
        __syncthreads();
        if (j < VOCAB) {
#pragma unroll 4
            for (int k = 0; k < 128; ++k) {
                unsigned long long wpk = pack2(W3[(size_t)(kc + k) * VOCAB + j]);
                const ulonglong2* yr = (const ulonglong2*)&ys[k][0];
#pragma unroll
                for (int b2 = 0; b2 < 16; ++b2) {
                    ulonglong2 v = yr[b2];                  // batches 4b2..4b2+3
                    acc[b2 * 2]     = fma2(wpk, v.x, acc[b2 * 2]);
                    acc[b2 * 2 + 1] = fma2(wpk, v.y, acc[b2 * 2 + 1]);
                }
            }
        }
    }
    if (j < VOCAB) {
        float bb = b3[j];
#pragma unroll
        for (int i = 0; i < 32; ++i) {
            out[(size_t)(2 * i)     * VOCAB + j] = lo2(acc[i]) + bb;
            out[(size_t)(2 * i + 1) * VOCAB + j] = hi2(acc[i]) + bb;
        }
    }
}

// ---------------- kernel 6: row-wise log_softmax ----------------
__global__ void __launch_bounds__(1024)
logsoftmax_kernel(const float* __restrict__ logits, float* __restrict__ out)
{
    __shared__ float red[32];
    const int b = blockIdx.x;
    const float* row  = logits + (size_t)b * VOCAB;
    float*       orow = out    + (size_t)b * VOCAB;
    const int tid = threadIdx.x;

    float m = -1e30f;
    for (int j = tid; j < VOCAB; j += 1024) m = fmaxf(m, row[j]);
#pragma unroll
    for (int o = 16; o; o >>= 1) m = fmaxf(m, __shfl_xor_sync(0xffffffffu, m, o));
    if ((tid & 31) == 0) red[tid >> 5] = m;
    __syncthreads();
    if (tid < 32) {
        float v = red[tid];
#pragma unroll
        for (int o = 16; o; o >>= 1) v = fmaxf(v, __shfl_xor_sync(0xffffffffu, v, o));
        red[tid] = v;
    }
    __syncthreads();
    m = red[0];

    float sum = 0.0f;
    for (int j = tid; j < VOCAB; j += 1024) sum += __expf(row[j] - m);
#pragma unroll
    for (int o = 16; o; o >>= 1) sum += __shfl_xor_sync(0xffffffffu, sum, o);
    __syncthreads();
    if ((tid & 31) == 0) red[tid >> 5] = sum;
    __syncthreads();
    if (tid < 32) {
        float v = red[tid];
#pragma unroll
        for (int o = 16; o; o >>= 1) v += __shfl_xor_sync(0xffffffffu, v, o);
        red[tid] = v;
    }
    __syncthreads();
    float lse = m + logf(red[0]);

    for (int j = tid; j < VOCAB; j += 1024) orow[j] = row[j] - lse;
}

// ---------------- launch ----------------
extern "C" void kernel_launch(void* const* d_in, const int* in_sizes, int n_in,
                              void* d_out, int out_size)
{
    const int*   inputs = (const int*)  d_in[0];
    const float* emb    = (const float*)d_in[1];
    const float* Wi     = (const float*)d_in[2];
    const float* Wh     = (const float*)d_in[3];
    const float* bvec   = (const float*)d_in[4];
    const float* W1     = (const float*)d_in[5];
    const float* b1     = (const float*)d_in[6];
    const float* W2     = (const float*)d_in[7];
    const float* b2     = (const float*)d_in[8];
    const float* W3     = (const float*)d_in[9];
    const float* b3     = (const float*)d_in[10];
    float* out = (float*)d_out;

    void *p_h = 0, *p_y1 = 0, *p_y2 = 0, *p_lg = 0;
    cudaGetSymbolAddress(&p_h,  g_hQ);     // final h in g_hQ[0], [q][u][b16]
    cudaGetSymbolAddress(&p_y1, g_y1);
    cudaGetSymbolAddress(&p_y2, g_y2);
    cudaGetSymbolAddress(&p_lg, g_logits);

    // 1. Z = emb[inputs] @ Wi + b  (time-parallel)
    embed_gemm_kernel<<<dim3(GATES / 128, (SEQ * BATCH) / 128), 256>>>(inputs, emb, Wi, bvec);

    // 2. persistent LSTM recurrence
    cudaFuncSetAttribute(lstm_kernel, cudaFuncAttributeMaxDynamicSharedMemorySize, LSTM_SMEM);
    lstm_kernel<<<NBLK, 256, LSTM_SMEM>>>(Wh);

    // 3/4. dense tanh layers (fc1 reads quarter-contiguous h)
    fc_tanh_kernel<1><<<BATCH, 512>>>((const float*)p_h,  W1, b1, (float*)p_y1);
    fc_tanh_kernel<0><<<BATCH, 512>>>((const float*)p_y1, W2, b2, (float*)p_y2);

    // 5. vocab projection
    logits_kernel<<<(VOCAB + 127) / 128, 128>>>((const float*)p_y2, W3, b3, (float*)p_lg);

    // 6. log_softmax
    logsoftmax_kernel<<<BATCH, 1024>>>((const float*)p_lg, out);
}

// round 16
// speedup vs baseline: 1.2385x; 1.0842x over previous
#include <cuda_runtime.h>
#include <math.h>

// ---------------- problem constants ----------------
#define BATCH   64
#define SEQ     512
#define EMB     256
#define HID     512
#define GATES   2048           // 4*HID
#define VOCAB   50257
#define NBLK    128            // persistent LSTM grid (<=148 SMs, 1 block/SM)

// ---------------- device scratch (static, no allocs) ----------------
__device__ float g_Z[(size_t)SEQ * BATCH * GATES];   // 256 MB: x@Wi + b, [s][b][4H]
__device__ float g_hQ[2][4][HID * 16];               // h, quarter-contiguous [q][u][b16]
__device__ float g_y1[BATCH * HID];
__device__ float g_y2[BATCH * HID];
__device__ float g_logits[(size_t)BATCH * VOCAB];
// 4 independent batch-quarter barriers, each on its own 128B line.
// Sense-reversing: after 512 steps (even) state returns to 0 -> replay-safe.
__device__ unsigned g_bar_cnt4[4 * 32];
__device__ unsigned g_bar_sense4[4 * 32];

// ---------------- packed f32x2 helpers (FFMA2 path, sm_100+) --------------
__device__ __forceinline__ unsigned long long fma2(unsigned long long a,
                                                   unsigned long long b,
                                                   unsigned long long c)
{
    unsigned long long d;
    asm("fma.rn.f32x2 %0, %1, %2, %3;" : "=l"(d) : "l"(a), "l"(b), "l"(c));
    return d;
}
__device__ __forceinline__ unsigned long long pack2(float x)
{
    unsigned long long d;
    unsigned u = __float_as_uint(x);
    asm("mov.b64 %0, {%1, %1};" : "=l"(d) : "r"(u));
    return d;
}
__device__ __forceinline__ float lo2(unsigned long long v) { return __uint_as_float((unsigned)v); }
__device__ __forceinline__ float hi2(unsigned long long v) { return __uint_as_float((unsigned)(v >> 32)); }

// ---------------- fast activations (MUFU.TANH) ----------------
__device__ __forceinline__ float tanh_fast(float x)
{
    float y;
    asm("tanh.approx.f32 %0, %1;" : "=f"(y) : "f"(x));
    return y;
}
__device__ __forceinline__ float sigmoid_fast(float x)
{
    return 0.5f * tanh_fast(0.5f * x) + 0.5f;
}

// ---------------- cp.async helpers ----------------
__device__ __forceinline__ void cp16(unsigned dst_u32, const void* src)
{
    asm volatile("cp.async.cg.shared.global [%0], [%1], 16;"
                 :: "r"(dst_u32), "l"(src) : "memory");
}
__device__ __forceinline__ void cp_commit()
{
    asm volatile("cp.async.commit_group;" ::: "memory");
}
__device__ __forceinline__ void cp_wait1()
{
    asm volatile("cp.async.wait_group 1;" ::: "memory");
}
__device__ __forceinline__ void cp_wait0()
{
    asm volatile("cp.async.wait_group 0;" ::: "memory");
}

// ---------------- group grid barrier (R7/R13-proven, n arrivals) ----------
__device__ __forceinline__ void grid_barrier_g(unsigned &sense, unsigned* cnt,
                                               unsigned* flag, unsigned n)
{
    __syncthreads();
    if (threadIdx.x == 0) {
        sense ^= 1u;
        unsigned old;
        asm volatile("atom.add.release.gpu.global.u32 %0, [%1], %2;"
                     : "=r"(old) : "l"(cnt), "r"(1u) : "memory");
        if (old == n - 1u) {
            asm volatile("st.global.relaxed.gpu.u32 [%0], %1;"
                         :: "l"(cnt), "r"(0u) : "memory");
            asm volatile("st.global.release.gpu.u32 [%0], %1;"
                         :: "l"(flag), "r"(sense) : "memory");
        } else {
            unsigned v;
            do {
                asm volatile("ld.global.acquire.gpu.u32 %0, [%1];"
                             : "=r"(v) : "l"(flag) : "memory");
            } while (v != sense);
        }
    }
    __syncthreads();
}

// ---------------- kernel 1: Z = gather(emb, inputs) @ Wi + b --------------
// (R2-proven, unchanged) 128x128 tile, K-chunks of 16, 8x8 thread tile, f32x2.
__global__ void __launch_bounds__(256, 2)
embed_gemm_kernel(const int* __restrict__ inputs, const float* __restrict__ emb,
                  const float* __restrict__ Wi, const float* __restrict__ bias)
{
    __shared__ float As[128][17];
    __shared__ float Bs[16][132];

    const int t  = threadIdx.x;
    const int mt = blockIdx.y;
    const int nt = blockIdx.x;
    const int tx = t & 15;
    const int ty = t >> 4;

    const int ra   = t >> 1;
    const int koff = (t & 1) * 8;
    const int rowg = mt * 128 + ra;
    const int s    = rowg >> 6;
    const int b    = rowg & 63;
    const float* erow = emb + (size_t)inputs[b * SEQ + s] * EMB;

    const int bkr  = t >> 4;
    const int bcol = (t & 15) * 8;

    unsigned long long acc[8][4];
#pragma unroll
    for (int i = 0; i < 8; ++i)
#pragma unroll
        for (int j = 0; j < 4; ++j) acc[i][j] = 0ULL;

    for (int k0 = 0; k0 < EMB; k0 += 16) {
        {
            float4 a0 = *(const float4*)(erow + k0 + koff);
            float4 a1 = *(const float4*)(erow + k0 + koff + 4);
            As[ra][koff + 0] = a0.x; As[ra][koff + 1] = a0.y;
            As[ra][koff + 2] = a0.z; As[ra][koff + 3] = a0.w;
            As[ra][koff + 4] = a1.x; As[ra][koff + 5] = a1.y;
            As[ra][koff + 6] = a1.z; As[ra][koff + 7] = a1.w;
        }
        {
            const float* wsrc = Wi + (size_t)(k0 + bkr) * GATES + nt * 128 + bcol;
            float4 b0v = *(const float4*)(wsrc);
            float4 b1v = *(const float4*)(wsrc + 4);
            *(float4*)&Bs[bkr][bcol]     = b0v;
            *(float4*)&Bs[bkr][bcol + 4] = b1v;
        }
        __syncthreads();

#pragma unroll
        for (int k = 0; k < 16; ++k) {
            unsigned long long pa[8];
#pragma unroll
            for (int i = 0; i < 4; ++i) {
                pa[i]     = pack2(As[ty * 4 + i][k]);
                pa[i + 4] = pack2(As[64 + ty * 4 + i][k]);
            }
            ulonglong2 b0v = *(const ulonglong2*)&Bs[k][tx * 4];
            ulonglong2 b1v = *(const ulonglong2*)&Bs[k][64 + tx * 4];
#pragma unroll
            for (int i = 0; i < 8; ++i) {
                acc[i][0] = fma2(pa[i], b0v.x, acc[i][0]);
                acc[i][1] = fma2(pa[i], b0v.y, acc[i][1]);
                acc[i][2] = fma2(pa[i], b1v.x, acc[i][2]);
                acc[i][3] = fma2(pa[i], b1v.y, acc[i][3]);
            }
        }
        __syncthreads();
    }

    float4 bb0 = *(const float4*)(bias + nt * 128 + tx * 4);
    float4 bb1 = *(const float4*)(bias + nt * 128 + 64 + tx * 4);
#pragma unroll
    for (int i = 0; i < 8; ++i) {
        int row = mt * 128 + ((i < 4) ? (ty * 4 + i) : (64 + ty * 4 + i - 4));
        float* zr = g_Z + (size_t)row * GATES + nt * 128;
        float4 v0, v1;
        v0.x = lo2(acc[i][0]) + bb0.x; v0.y = hi2(acc[i][0]) + bb0.y;
        v0.z = lo2(acc[i][1]) + bb0.z; v0.w = hi2(acc[i][1]) + bb0.w;
        v1.x = lo2(acc[i][2]) + bb1.x; v1.y = hi2(acc[i][2]) + bb1.y;
        v1.z = lo2(acc[i][3]) + bb1.z; v1.w = hi2(acc[i][3]) + bb1.w;
        *(float4*)(zr + tx * 4)      = v0;
        *(float4*)(zr + 64 + tx * 4) = v1;
    }
}

// ---------------- kernel 2: persistent LSTM over 512 steps ----------------
// (R13-proven core) 128 blocks = 32 unit-groups x 4 batch-quarters;
// block = 16 units x 16 batches; warp = kc strip (broadcast LDS);
// warp-private cp.async staging; quarter-contiguous h; quarter barriers.
// NEW vs R13: TWO-PHASE staging. Lane j-chunks partition exactly by strip
// half (j<4 -> strip k in [0,32), j>=4 -> [32,64)). Two commit groups;
// wait_group(1)+syncwarp releases the first half for compute while the
// second half drains under the first 32 fma2 iterations.
#define LSTM_SMEM (32768 + 131072 + 36864)

__global__ void __launch_bounds__(256, 1)
lstm_kernel(const float* __restrict__ Wh)
{
    extern __shared__ float sm[];
    float4*     h_s4 = (float4*)sm;                           // [512][4]
    ulonglong2* Whs  = (ulonglong2*)((char*)sm + 32768);      // [512][16]
    ulonglong2* red  = (ulonglong2*)((char*)sm + 163840);     // [256 p][9]

    const int tid  = threadIdx.x;
    const int kc   = tid >> 5;           // warp id = k-strip 0..7 (64 k each)
    const int lane = tid & 31;
    const int up   = lane >> 2;          // unit pair 0..7 (units 2up, 2up+1)
    const int bg   = lane & 3;           // batch group 0..3 (4 batches)
    const int ub   = blockIdx.x >> 2;    // unit group 0..31 (16 units)
    const int q    = blockIdx.x & 3;     // batch quarter 0..3 (16 batches)
    const unsigned h_s_u32 = (unsigned)__cvta_generic_to_shared(h_s4);

    unsigned* cntp  = &g_bar_cnt4[q * 32];
    unsigned* snsp  = &g_bar_sense4[q * 32];

    // epilogue ownership: pair p = tid -> unit u_local, batch b_local
    const int eul = tid >> 4;            // 0..15
    const int ebl = tid & 15;            // 0..15
    const int euu = ub * 16 + eul;       // global unit
    const int egb = q * 16 + ebl;        // global batch

    // stage Wh slice once: Whs[k*16+u] = {(wi,wf),(wg,wo)} for col = ub*16+u
    for (int i = tid; i < HID * 16; i += 256) {
        int k = i >> 4, u2 = i & 15;
        const float* w = Wh + (size_t)k * GATES + ub * 16 + u2;
        float4 v = make_float4(w[0], w[512], w[1024], w[1536]);
        Whs[i] = *(ulonglong2*)&v;
    }

    float c = 0.0f;                      // cell state of pair p = tid
    unsigned sense = 0;
    __syncthreads();

    const ulonglong2* wp = Whs  + kc * 1024 + up * 2;  // iter i: wp[i*16], +1
    const float4*     hp = h_s4 + kc * 256 + bg;       // iter i: hp[i*4]

    // warp-private staging: warp kc owns f4-chunks [kc*256, kc*256+256).
    // Quarter slice is DENSE: chunk index == smem f4 index == src f4 index.
    const int cbase = kc * 256 + lane;                 // 8 chunks per lane

    // Z prefetch for step 0 (gates for pair p)
    const float* z0 = g_Z + (size_t)egb * GATES + euu;
    float zi = __ldcg(z0), zf = __ldcg(z0 + 512);
    float zg = __ldcg(z0 + 1024), zo = __ldcg(z0 + 1536);

    for (int s = 0; s < SEQ; ++s) {
        unsigned long long aif[2][4] = {{0,0,0,0},{0,0,0,0}};
        unsigned long long ago[2][4] = {{0,0,0,0},{0,0,0,0}};

        if (s > 0) {
            // ---- two-phase warp-private staging of this warp's h strip ----
            const float4* src4 = (const float4*)g_hQ[s & 1][q];
            // phase A: j=0..3 -> strip-local f4 idx [0,128) -> k in [0,32)
#pragma unroll
            for (int j = 0; j < 4; ++j) {
                int chunk = cbase + j * 32;
                cp16(h_s_u32 + chunk * 16, src4 + chunk);
            }
            cp_commit();
            // phase B: j=4..7 -> k in [32,64)
#pragma unroll
            for (int j = 4; j < 8; ++j) {
                int chunk = cbase + j * 32;
                cp16(h_s_u32 + chunk * 16, src4 + chunk);
            }
            cp_commit();

            cp_wait1();        // phase A landed for this lane
            __syncwarp();      // ... for all 32 lanes -> strip k<32 complete

            // ---- mainloop first half (k in [0,32)); phase B drains under it
#pragma unroll 4
            for (int i = 0; i < 32; ++i) {
                ulonglong2 w0 = wp[i * 16];      // unit 2up   (wi,wf),(wg,wo)
                ulonglong2 w1 = wp[i * 16 + 1];  // unit 2up+1
                float4     hv = hp[i * 4];       // 4 batches
                unsigned long long p;
                p = pack2(hv.x);
                aif[0][0] = fma2(p, w0.x, aif[0][0]); ago[0][0] = fma2(p, w0.y, ago[0][0]);
                aif[1][0] = fma2(p, w1.x, aif[1][0]); ago[1][0] = fma2(p, w1.y, ago[1][0]);
                p = pack2(hv.y);
                aif[0][1] = fma2(p, w0.x, aif[0][1]); ago[0][1] = fma2(p, w0.y, ago[0][1]);
                aif[1][1] = fma2(p, w1.x, aif[1][1]); ago[1][1] = fma2(p, w1.y, ago[1][1]);
                p = pack2(hv.z);
                aif[0][2] = fma2(p, w0.x, aif[0][2]); ago[0][2] = fma2(p, w0.y, ago[0][2]);
                aif[1][2] = fma2(p, w1.x, aif[1][2]); ago[1][2] = fma2(p, w1.y, ago[1][2]);
                p = pack2(hv.w);
                aif[0][3] = fma2(p, w0.x, aif[0][3]); ago[0][3] = fma2(p, w0.y, ago[0][3]);
                aif[1][3] = fma2(p, w1.x, aif[1][3]); ago[1][3] = fma2(p, w1.y, ago[1][3]);
            }

            cp_wait0();        // phase B landed for this lane
            __syncwarp();      // strip complete

            // ---- mainloop second half (k in [32,64)) ----
#pragma unroll 4
            for (int i = 32; i < 64; ++i) {
                ulonglong2 w0 = wp[i * 16];
                ulonglong2 w1 = wp[i * 16 + 1];
                float4     hv = hp[i * 4];
                unsigned long long p;
                p = pack2(hv.x);
                aif[0][0] = fma2(p, w0.x, aif[0][0]); ago[0][0] = fma2(p, w0.y, ago[0][0]);
                aif[1][0] = fma2(p, w1.x, aif[1][0]); ago[1][0] = fma2(p, w1.y, ago[1][0]);
                p = pack2(hv.y);
                aif[0][1] = fma2(p, w0.x, aif[0][1]); ago[0][1] = fma2(p, w0.y, ago[0][1]);
                aif[1][1] = fma2(p, w1.x, aif[1][1]); ago[1][1] = fma2(p, w1.y, ago[1][1]);
                p = pack2(hv.z);
                aif[0][2] = fma2(p, w0.x, aif[0][2]); ago[0][2] = fma2(p, w0.y, ago[0][2]);
                aif[1][2] = fma2(p, w1.x, aif[1][2]); ago[1][2] = fma2(p, w1.y, ago[1][2]);
                p = pack2(hv.w);
                aif[0][3] = fma2(p, w0.x, aif[0][3]); ago[0][3] = fma2(p, w0.y, ago[0][3]);
                aif[1][3] = fma2(p, w1.x, aif[1][3]); ago[1][3] = fma2(p, w1.y, ago[1][3]);
            }
        }

        // ---- write partials to skewed red[p*9 + kc] ----
#pragma unroll
        for (int uo = 0; uo < 2; ++uo)
#pragma unroll
            for (int bi = 0; bi < 4; ++bi) {
                int p = (2 * up + uo) * 16 + bg * 4 + bi;
                red[p * 9 + kc] = make_ulonglong2(aif[uo][bi], ago[uo][bi]);
            }
        __syncthreads();

        // ---- reduce 8 kc partials for pair p = tid; epilogue ----
        {
            float fi = zi, ff = zf, fg_ = zg, fo = zo;
#pragma unroll
            for (int k8 = 0; k8 < 8; ++k8) {
                ulonglong2 v = red[tid * 9 + k8];
                fi += lo2(v.x); ff += hi2(v.x);
                fg_ += lo2(v.y); fo += hi2(v.y);
            }
            float ig  = sigmoid_fast(fi);
            float fg2 = sigmoid_fast(ff);
            float gg  = tanh_fast(fg_);
            float og  = sigmoid_fast(fo);
            c = fg2 * c + ig * gg;
            float hv = og * tanh_fast(c);
            // quarter-contiguous store: [q][u][b16]; final h in g_hQ[0]
            g_hQ[(s + 1) & 1][q][euu * 16 + ebl] = hv;
        }

        // ---- prefetch Z for step s+1 (hides DRAM latency behind barrier) --
        if (s + 1 < SEQ) {
            const float* z = g_Z + ((size_t)(s + 1) * BATCH + egb) * GATES + euu;
            zi = __ldcg(z);        zf = __ldcg(z + 512);
            zg = __ldcg(z + 1024); zo = __ldcg(z + 1536);
        }

        grid_barrier_g(sense, cntp, snsp, 32u);   // only this batch quarter
    }
}

// ---------------- kernels 3/4: y = tanh(x @ W + bias), 64x512 --------------
// Block = one batch row (64 blocks x 512 threads); x row staged in smem.
// KM=1: x is quarter-contiguous h (g_hQ[0]): x[(b>>4)*8192 + (b&15) + k*16].
// KM=0: x is batch-major [b][k]: x[b*512 + k].
template<int KM>
__global__ void __launch_bounds__(512)
fc_tanh_kernel(const float* __restrict__ x, const float* __restrict__ W,
               const float* __restrict__ bias, float* __restrict__ y)
{
    __shared__ float xs[HID];
    const int b = blockIdx.x;
    const int j = threadIdx.x;

    if (KM == 1)
        xs[j] = x[(b >> 4) * 8192 + (b & 15) + j * 16];
    else
        xs[j] = x[b * HID + j];
    __syncthreads();

    float a0 = 0.f, a1 = 0.f, a2 = 0.f, a3 = 0.f;
#pragma unroll 4
    for (int k = 0; k < HID; k += 4) {
        a0 += xs[k + 0] * W[(size_t)(k + 0) * HID + j];
        a1 += xs[k + 1] * W[(size_t)(k + 1) * HID + j];
        a2 += xs[k + 2] * W[(size_t)(k + 2) * HID + j];
        a3 += xs[k + 3] * W[(size_t)(k + 3) * HID + j];
    }
    y[b * HID + j] = tanhf((a0 + a1) + (a2 + a3) + bias[j]);
}

// ---------------- kernel 5: logits = y2 @ W3 + b3 (f32x2 accumulators) -----
__global__ void __launch_bounds__(128)
logits_kernel(const float* __restrict__ y, const float* __restrict__ W3,
              const float* __restrict__ b3, float* __restrict__ out)
{
    __shared__ __align__(16) float ys[128][68];   // [k][b], row = 272B (16B-mult)
    const int j = blockIdx.x * 128 + threadIdx.x;

    unsigned long long acc[32];
#pragma unroll
    for (int i = 0; i < 32; ++i) acc[i] = 0ULL;

    for (int kc = 0; kc < HID; kc += 128) {
        __syncthreads();
        for (int qq = threadIdx.x; qq < 128 * 64; qq += 128) {
            int b = qq >> 7, k = qq & 127;
            ys[k][b] = y[b * HID + kc + k];
        }
        __syncthreads();
        if (j < VOCAB) {
#pragma unroll 4
            for (int k = 0; k < 128; ++k) {
                unsigned long long wpk = pack2(W3[(size_t)(kc + k) * VOCAB + j]);
                const ulonglong2* yr = (const ulonglong2*)&ys[k][0];
#pragma unroll
                for (int b2 = 0; b2 < 16; ++b2) {
                    ulonglong2 v = yr[b2];                  // batches 4b2..4b2+3
                    acc[b2 * 2]     = fma2(wpk, v.x, acc[b2 * 2]);
                    acc[b2 * 2 + 1] = fma2(wpk, v.y, acc[b2 * 2 + 1]);
                }
            }
        }
    }
    if (j < VOCAB) {
        float bb = b3[j];
#pragma unroll
        for (int i = 0; i < 32; ++i) {
            out[(size_t)(2 * i)     * VOCAB + j] = lo2(acc[i]) + bb;
            out[(size_t)(2 * i + 1) * VOCAB + j] = hi2(acc[i]) + bb;
        }
    }
}

// ---------------- kernel 6: row-wise log_softmax ----------------
__global__ void __launch_bounds__(1024)
logsoftmax_kernel(const float* __restrict__ logits, float* __restrict__ out)
{
    __shared__ float red[32];
    const int b = blockIdx.x;
    const float* row  = logits + (size_t)b * VOCAB;
    float*       orow = out    + (size_t)b * VOCAB;
    const int tid = threadIdx.x;

    float m = -1e30f;
    for (int j = tid; j < VOCAB; j += 1024) m = fmaxf(m, row[j]);
#pragma unroll
    for (int o = 16; o; o >>= 1) m = fmaxf(m, __shfl_xor_sync(0xffffffffu, m, o));
    if ((tid & 31) == 0) red[tid >> 5] = m;
    __syncthreads();
    if (tid < 32) {
        float v = red[tid];
#pragma unroll
        for (int o = 16; o; o >>= 1) v = fmaxf(v, __shfl_xor_sync(0xffffffffu, v, o));
        red[tid] = v;
    }
    __syncthreads();
    m = red[0];

    float sum = 0.0f;
    for (int j = tid; j < VOCAB; j += 1024) sum += __expf(row[j] - m);
#pragma unroll
    for (int o = 16; o; o >>= 1) sum += __shfl_xor_sync(0xffffffffu, sum, o);
    __syncthreads();
    if ((tid & 31) == 0) red[tid >> 5] = sum;
    __syncthreads();
    if (tid < 32) {
        float v = red[tid];
#pragma unroll
        for (int o = 16; o; o >>= 1) v += __shfl_xor_sync(0xffffffffu, v, o);
        red[tid] = v;
    }
    __syncthreads();
    float lse = m + logf(red[0]);

    for (int j = tid; j < VOCAB; j += 1024) orow[j] = row[j] - lse;
}

// ---------------- launch ----------------
extern "C" void kernel_launch(void* const* d_in, const int* in_sizes, int n_in,
                              void* d_out, int out_size)
{
    const int*   inputs = (const int*)  d_in[0];
    const float* emb    = (const float*)d_in[1];
    const float* Wi     = (const float*)d_in[2];
    const float* Wh     = (const float*)d_in[3];
    const float* bvec   = (const float*)d_in[4];
    const float* W1     = (const float*)d_in[5];
    const float* b1     = (const float*)d_in[6];
    const float* W2     = (const float*)d_in[7];
    const float* b2     = (const float*)d_in[8];
    const float* W3     = (const float*)d_in[9];
    const float* b3     = (const float*)d_in[10];
    float* out = (float*)d_out;

    void *p_h = 0, *p_y1 = 0, *p_y2 = 0, *p_lg = 0;
    cudaGetSymbolAddress(&p_h,  g_hQ);     // final h in g_hQ[0], [q][u][b16]
    cudaGetSymbolAddress(&p_y1, g_y1);
    cudaGetSymbolAddress(&p_y2, g_y2);
    cudaGetSymbolAddress(&p_lg, g_logits);

    // 1. Z = emb[inputs] @ Wi + b  (time-parallel)
    embed_gemm_kernel<<<dim3(GATES / 128, (SEQ * BATCH) / 128), 256>>>(inputs, emb, Wi, bvec);

    // 2. persistent LSTM recurrence
    cudaFuncSetAttribute(lstm_kernel, cudaFuncAttributeMaxDynamicSharedMemorySize, LSTM_SMEM);
    lstm_kernel<<<NBLK, 256, LSTM_SMEM>>>(Wh);

    // 3/4. dense tanh layers (fc1 reads quarter-contiguous h)
    fc_tanh_kernel<1><<<BATCH, 512>>>((const float*)p_h,  W1, b1, (float*)p_y1);
    fc_tanh_kernel<0><<<BATCH, 512>>>((const float*)p_y1, W2, b2, (float*)p_y2);

    // 5. vocab projection
    logits_kernel<<<(VOCAB + 127) / 128, 128>>>((const float*)p_y2, W3, b3, (float*)p_lg);

    // 6. log_softmax
    logsoftmax_kernel<<<BATCH, 1024>>>((const float*)p_lg, out);
}